// round 15
// baseline (speedup 1.0000x reference)
#include <cuda_runtime.h>
#include <cuda_fp16.h>
#include <cstdint>
#include <cfloat>

// Problem constants
#define NN     50000
#define EIN    800000
#define ET     (EIN + NN)
#define IND    128
#define HEADS  4
#define HID    64
#define HC     256
#define OUTD   64
#define NEG_SLOPE 0.2f

#define SCAN_B 256
#define NBLK   ((NN + SCAN_B - 1) / SCAN_B)

// ---------------- device scratch ----------------
__device__ __align__(16) __half g_x16 [(size_t)NN * IND];
__device__ __align__(16) __half g_xh16[(size_t)NN * HC];
__device__ __align__(16) __half g_h16 [(size_t)NN * HC];
__device__ float g_asrcA[(size_t)NN * HEADS];
__device__ float g_adstA[(size_t)NN * HEADS];
__device__ float g_asrcB[(size_t)NN * HEADS];
__device__ float g_adstB[(size_t)NN * HEADS];
__device__ __align__(16) __half g_w1[256 * 128];
__device__ __align__(16) __half g_w2[256 * 256];
__device__ __align__(16) __half g_wf[64 * 256];
__device__ int   g_deg [NN];
__device__ int   g_off [NN + 1];
__device__ int   g_cur [NN];
__device__ int   g_part[NBLK];
__device__ int   g_csrc[ET];
__device__ int   g_src [ET];
__device__ int   g_dst [ET];
__device__ int   g_is64;

__device__ __forceinline__ float lrelu(float v) {
    return v >= 0.f ? v : NEG_SLOPE * v;
}
__device__ __forceinline__ uint32_t smem_u32(const void* p) {
    uint32_t a;
    asm("{ .reg .u64 t; cvta.to.shared.u64 t, %1; cvt.u32.u64 %0, t; }" : "=r"(a) : "l"(p));
    return a;
}
__device__ __forceinline__ void cp_async16(uint32_t dst, const void* src, bool pred) {
    int sz = pred ? 16 : 0;
    asm volatile("cp.async.cg.shared.global [%0], [%1], 16, %2;"
                 :: "r"(dst), "l"(src), "r"(sz) : "memory");
}
#define CP_COMMIT() asm volatile("cp.async.commit_group;" ::: "memory")
#define CP_WAIT0()  asm volatile("cp.async.wait_group 0;" ::: "memory")
#define CP_WAIT1()  asm volatile("cp.async.wait_group 1;" ::: "memory")

// ---------------- fused prep ----------------
__global__ void prep_kernel(const long long* __restrict__ ei,
                            const float* __restrict__ x,
                            const float* __restrict__ W1,
                            const float* __restrict__ W2,
                            const float* __restrict__ Wfc) {
    int i = blockIdx.x * blockDim.x + threadIdx.x;
    if (i == 0) {
        int is64 = 1;
        for (int k = 0; k < 16; k++) {
            long long v = ei[k];
            if (v < 0 || v >= (long long)NN) { is64 = 0; break; }
        }
        g_is64 = is64;
        g_off[NN] = ET;
    }
    if (i < NN) g_deg[i] = 0;
    if (i < NN * HEADS) {
        g_asrcA[i] = 0.f; g_adstA[i] = 0.f;
        g_asrcB[i] = 0.f; g_adstB[i] = 0.f;
    }
    const int s1 = 128 * 256, s2 = s1 + 256 * 256, s3 = s2 + 256 * 64;
    if (i < s1) {
        int k = i / 256, n = i % 256;
        g_w1[n * 128 + k] = __float2half(W1[i]);
    } else if (i < s2) {
        int j = i - s1;
        int k = j / 256, n = j % 256;
        g_w2[n * 256 + k] = __float2half(W2[j]);
    } else if (i < s3) {
        int j = i - s2;
        int k = j / 64, n = j % 64;
        g_wf[n * 256 + k] = __float2half(Wfc[j]);
    }
    if (i < NN * IND / 4) {
        float4 v = *(const float4*)(x + (size_t)i * 4);
        __half2 h01 = __floats2half2_rn(v.x, v.y);
        __half2 h23 = __floats2half2_rn(v.z, v.w);
        uint2 u;
        u.x = *(uint32_t*)&h01;
        u.y = *(uint32_t*)&h23;
        *(uint2*)(g_x16 + (size_t)i * 4) = u;
    }
}

__global__ void convert_hist_kernel(const void* __restrict__ ei) {
    int i = blockIdx.x * blockDim.x + threadIdx.x;
    if (i >= ET) return;
    int s, d;
    if (i < EIN) {
        if (g_is64) {
            const long long* p = (const long long*)ei;
            s = (int)p[i];
            d = (int)p[EIN + i];
        } else {
            const int* p = (const int*)ei;
            s = p[i];
            d = p[EIN + i];
        }
    } else {
        s = d = i - EIN;
    }
    g_src[i] = s;
    g_dst[i] = d;
    atomicAdd(&g_deg[d], 1);
}

// ---------------- mma.sync fp16 + ldmatrix helpers ----------------
__device__ __forceinline__ void mma16816(float* c, const uint32_t* a, const uint32_t* b) {
    asm volatile(
        "mma.sync.aligned.m16n8k16.row.col.f32.f16.f16.f32 "
        "{%0,%1,%2,%3}, {%4,%5,%6,%7}, {%8,%9}, {%0,%1,%2,%3};"
        : "+f"(c[0]), "+f"(c[1]), "+f"(c[2]), "+f"(c[3])
        : "r"(a[0]), "r"(a[1]), "r"(a[2]), "r"(a[3]), "r"(b[0]), "r"(b[1]));
}
__device__ __forceinline__ void ldsm_x4(uint32_t* r, uint32_t addr) {
    asm volatile("ldmatrix.sync.aligned.m8n8.x4.shared.b16 {%0,%1,%2,%3}, [%4];"
                 : "=r"(r[0]), "=r"(r[1]), "=r"(r[2]), "=r"(r[3]) : "r"(addr));
}

// ---------------- tensor-core GEMM: 128 x 64 tile, 3-stage cp.async ----------------
template<int KTOT, int NTOT, bool BIAS, bool ALPHA, bool OUTF16>
__global__ void __launch_bounds__(256, 3)
gemm_mma_kernel(const __half* __restrict__ A16,
                const __half* __restrict__ B,
                void* __restrict__ Cptr,
                const float* __restrict__ bias,
                const float* __restrict__ aw_src,
                const float* __restrict__ aw_dst,
                float* __restrict__ asrc_out,
                float* __restrict__ adst_out) {
    constexpr int BN  = 64;
    constexpr int RS  = 40;
    constexpr int NF  = 2;
    constexpr int NC  = KTOT / 32;
    constexpr uint32_t BUF_BYTES = (uint32_t)(128 + BN) * RS * 2u;

    __shared__ __half sm[3 * (128 + BN) * RS];   // 45 KB

    const int tid  = threadIdx.x;
    const int wid  = tid >> 5, lane = tid & 31;
    const int wm   = wid & 1, wn = wid >> 1;
    const int row0 = blockIdx.y * 128;
    const int col0 = blockIdx.x * BN;

    float acc[4][NF][4];
    #pragma unroll
    for (int i = 0; i < 4; i++)
        #pragma unroll
        for (int j = 0; j < NF; j++)
            #pragma unroll
            for (int q = 0; q < 4; q++) acc[i][j][q] = 0.f;

    const uint32_t smBase = smem_u32(sm);

    auto stage = [&](int c) {
        uint32_t base = smBase + (uint32_t)(c % 3) * BUF_BYTES;
        #pragma unroll
        for (int q = 0; q < 2; q++) {
            int idx = tid + q * 256;
            int row = idx >> 2, c8 = (idx & 3) * 8;
            int gr = row0 + row;
            bool ok = (gr < NN);
            const __half* src = A16 + (size_t)(ok ? gr : 0) * KTOT + c * 32 + c8;
            cp_async16(base + (uint32_t)(row * RS + c8) * 2u, src, ok);
        }
        {
            int row = tid >> 2, c8 = (tid & 3) * 8;
            cp_async16(base + (uint32_t)((128 + row) * RS + c8) * 2u,
                       B + (size_t)(col0 + row) * KTOT + c * 32 + c8, true);
        }
        CP_COMMIT();
    };

    stage(0);
    if (NC > 1) stage(1);

    const int arow = (lane >> 2);
    const int acol = (lane & 3) * 2;
    const int aLaneRow = wm * 64 + (lane & 7) + ((lane >> 3) & 1) * 8;
    const uint32_t aLaneK = (lane >> 4) * 16;
    const int bLaneRow = 128 + wn * 16 + ((lane >> 4) & 1) * 8 + (lane & 7);
    const uint32_t bLaneH = ((lane >> 3) & 1) * 16;

    for (int c = 0; c < NC; c++) {
        if (c + 1 < NC) CP_WAIT1(); else CP_WAIT0();
        __syncthreads();
        if (c + 2 < NC) stage(c + 2);

        const uint32_t base = smBase + (uint32_t)(c % 3) * BUF_BYTES;
        #pragma unroll
        for (int ks = 0; ks < 2; ks++) {
            uint32_t br[4];
            ldsm_x4(br, base + (uint32_t)bLaneRow * 80u + (uint32_t)ks * 32u + bLaneH);
            uint32_t b0[2] = {br[0], br[1]};
            uint32_t b1[2] = {br[2], br[3]};
            #pragma unroll
            for (int i = 0; i < 4; i++) {
                uint32_t a[4];
                ldsm_x4(a, base + (uint32_t)(aLaneRow + i * 16) * 80u + (uint32_t)ks * 32u + aLaneK);
                mma16816(acc[i][0], a, b0);
                mma16816(acc[i][1], a, b1);
            }
        }
        __syncthreads();
    }

    // ---- epilogue: write C ----
    #pragma unroll
    for (int i = 0; i < 4; i++) {
        int r = row0 + wm * 64 + i * 16 + arow;
        #pragma unroll
        for (int j = 0; j < NF; j++) {
            int c = col0 + wn * 16 + j * 8 + acol;
            if (OUTF16) {
                __half* C16 = (__half*)Cptr;
                if (r < NN) {
                    __half2 v = __floats2half2_rn(acc[i][j][0], acc[i][j][1]);
                    *(__half2*)(C16 + (size_t)r * NTOT + c) = v;
                }
                if (r + 8 < NN) {
                    __half2 v = __floats2half2_rn(acc[i][j][2], acc[i][j][3]);
                    *(__half2*)(C16 + (size_t)(r + 8) * NTOT + c) = v;
                }
            } else {
                float* C = (float*)Cptr;
                float bx = 0.f, by = 0.f;
                if (BIAS) { bx = bias[c]; by = bias[c + 1]; }
                if (r < NN) {
                    float2 v = make_float2(acc[i][j][0] + bx, acc[i][j][1] + by);
                    *(float2*)(C + (size_t)r * NTOT + c) = v;
                }
                if (r + 8 < NN) {
                    float2 v = make_float2(acc[i][j][2] + bx, acc[i][j][3] + by);
                    *(float2*)(C + (size_t)(r + 8) * NTOT + c) = v;
                }
            }
        }
    }

    // ---- epilogue: fused alpha accumulation (NTOT == HC case) ----
    if (ALPHA) {
        const int hw = col0 >> 6;
        #pragma unroll
        for (int i = 0; i < 4; i++) {
            float ss0 = 0.f, sd0 = 0.f, ss1 = 0.f, sd1 = 0.f;
            #pragma unroll
            for (int j = 0; j < NF; j++) {
                #pragma unroll
                for (int qq = 0; qq < 2; qq++) {
                    int c = col0 + wn * 16 + j * 8 + acol + qq;
                    float ws = aw_src[c], wd = aw_dst[c];
                    ss0 += acc[i][j][qq]     * ws;
                    sd0 += acc[i][j][qq]     * wd;
                    ss1 += acc[i][j][2 + qq] * ws;
                    sd1 += acc[i][j][2 + qq] * wd;
                }
            }
            #pragma unroll
            for (int o = 1; o < 4; o <<= 1) {
                ss0 += __shfl_xor_sync(0xffffffffu, ss0, o);
                sd0 += __shfl_xor_sync(0xffffffffu, sd0, o);
                ss1 += __shfl_xor_sync(0xffffffffu, ss1, o);
                sd1 += __shfl_xor_sync(0xffffffffu, sd1, o);
            }
            if ((lane & 3) == 0) {
                int r = row0 + wm * 64 + i * 16 + arow;
                if (r < NN) {
                    atomicAdd(&asrc_out[r * 4 + hw], ss0);
                    atomicAdd(&adst_out[r * 4 + hw], sd0);
                }
                if (r + 8 < NN) {
                    atomicAdd(&asrc_out[(r + 8) * 4 + hw], ss1);
                    atomicAdd(&adst_out[(r + 8) * 4 + hw], sd1);
                }
            }
        }
    }
}

// ---------------- scan (2-phase, device-wide) ----------------
__device__ __forceinline__ int block_excl_scan(int v, int t, int* tot) {
    __shared__ int ws[8];
    int lane = t & 31, w = t >> 5;
    int x = v;
    #pragma unroll
    for (int o = 1; o < 32; o <<= 1) {
        int y = __shfl_up_sync(0xffffffffu, x, o);
        if (lane >= o) x += y;
    }
    if (lane == 31) ws[w] = x;
    __syncthreads();
    if (w == 0) {
        int z = (lane < 8) ? ws[lane] : 0;
        #pragma unroll
        for (int o = 1; o < 8; o <<= 1) {
            int y = __shfl_up_sync(0xffffffffu, z, o);
            if (lane >= o) z += y;
        }
        if (lane < 8) ws[lane] = z;
    }
    __syncthreads();
    int base = (w > 0) ? ws[w - 1] : 0;
    int total = ws[7];
    __syncthreads();
    *tot = total;
    return base + x - v;
}

__global__ void scan_partial_kernel() {
    int i = blockIdx.x * SCAN_B + threadIdx.x;
    int v = (i < NN) ? g_deg[i] : 0;
    int tot;
    block_excl_scan(v, threadIdx.x, &tot);
    if (threadIdx.x == 0) g_part[blockIdx.x] = tot;
}

__global__ void scan_final_kernel() {
    __shared__ int sred[8];
    __shared__ int sbase;
    int t = threadIdx.x;
    int lane = t & 31, w = t >> 5;

    int pv = (t < blockIdx.x && t < NBLK) ? g_part[t] : 0;
    #pragma unroll
    for (int o = 16; o > 0; o >>= 1) pv += __shfl_xor_sync(0xffffffffu, pv, o);
    if (lane == 0) sred[w] = pv;
    __syncthreads();
    if (t == 0) {
        int s = 0;
        #pragma unroll
        for (int q = 0; q < 8; q++) s += sred[q];
        sbase = s;
    }
    __syncthreads();

    int i = blockIdx.x * SCAN_B + t;
    int v = (i < NN) ? g_deg[i] : 0;
    int tot;
    int excl = block_excl_scan(v, t, &tot) + sbase;
    if (i < NN) {
        g_off[i] = excl;
        g_cur[i] = excl;
    }
}

__global__ void scatter_kernel() {
    int i = blockIdx.x * blockDim.x + threadIdx.x;
    if (i >= ET) return;
    int d = g_dst[i];
    int pos = atomicAdd(&g_cur[d], 1);
    g_csrc[pos] = g_src[i];
}

// ---------------- fused softmax + aggregation (exp-deduplicated) ----------------
// pass A: per-head max (no exp). pass C: chunks of 32 edges; owner lane computes
// unnormalized u = exp(e - m) ONCE per edge (4 exps), accumulates denominator;
// all lanes read u via shfl and accumulate u * msg. Normalize in epilogue.
__global__ void agg_kernel(const __half* __restrict__ msg,
                           const float* __restrict__ asrc,
                           const float* __restrict__ adstv,
                           const float* __restrict__ bias,
                           __half* __restrict__ hout) {
    int warp = (blockIdx.x * blockDim.x + threadIdx.x) >> 5;
    int lane = threadIdx.x & 31;
    if (warp >= NN) return;
    const int d = warp;
    const int beg = g_off[d], end = g_off[d + 1];
    const float4 ad = *(const float4*)(adstv + (size_t)d * 4);

    // ---- pass A: per-head max ----
    float m0 = -FLT_MAX, m1 = -FLT_MAX, m2 = -FLT_MAX, m3 = -FLT_MAX;
    for (int p = beg + lane; p < end; p += 32) {
        int s = g_csrc[p];
        float4 as = *(const float4*)(asrc + (size_t)s * 4);
        m0 = fmaxf(m0, lrelu(as.x + ad.x));
        m1 = fmaxf(m1, lrelu(as.y + ad.y));
        m2 = fmaxf(m2, lrelu(as.z + ad.z));
        m3 = fmaxf(m3, lrelu(as.w + ad.w));
    }
    #pragma unroll
    for (int o = 16; o > 0; o >>= 1) {
        m0 = fmaxf(m0, __shfl_xor_sync(0xffffffffu, m0, o));
        m1 = fmaxf(m1, __shfl_xor_sync(0xffffffffu, m1, o));
        m2 = fmaxf(m2, __shfl_xor_sync(0xffffffffu, m2, o));
        m3 = fmaxf(m3, __shfl_xor_sync(0xffffffffu, m3, o));
    }

    // ---- pass C: chunked unnormalized accumulation ----
    const int h = lane >> 3;
    float den0 = 0.f, den1 = 0.f, den2 = 0.f, den3 = 0.f;
    float acc[8] = {};
    const __half* xrow = msg + (size_t)lane * 8;

    for (int p0 = beg; p0 < end; p0 += 32) {
        int p = p0 + lane;
        float u0 = 0.f, u1 = 0.f, u2 = 0.f, u3 = 0.f;
        int sreg = 0;
        if (p < end) {
            int s = g_csrc[p];
            sreg = s;
            float4 as = *(const float4*)(asrc + (size_t)s * 4);
            u0 = __expf(lrelu(as.x + ad.x) - m0);
            u1 = __expf(lrelu(as.y + ad.y) - m1);
            u2 = __expf(lrelu(as.z + ad.z) - m2);
            u3 = __expf(lrelu(as.w + ad.w) - m3);
            den0 += u0; den1 += u1; den2 += u2; den3 += u3;
        }
        int cnt = min(32, end - p0);
        for (int q = 0; q < cnt; q++) {
            int s   = __shfl_sync(0xffffffffu, sreg, q);
            float q0 = __shfl_sync(0xffffffffu, u0, q);
            float q1 = __shfl_sync(0xffffffffu, u1, q);
            float q2 = __shfl_sync(0xffffffffu, u2, q);
            float q3 = __shfl_sync(0xffffffffu, u3, q);
            float a = (h == 0) ? q0 : (h == 1) ? q1 : (h == 2) ? q2 : q3;
            uint4 v = *(const uint4*)(xrow + (size_t)s * HC);
            __half2 h01 = *(__half2*)&v.x;
            __half2 h23 = *(__half2*)&v.y;
            __half2 h45 = *(__half2*)&v.z;
            __half2 h67 = *(__half2*)&v.w;
            float2 f01 = __half22float2(h01);
            float2 f23 = __half22float2(h23);
            float2 f45 = __half22float2(h45);
            float2 f67 = __half22float2(h67);
            acc[0] = fmaf(a, f01.x, acc[0]);
            acc[1] = fmaf(a, f01.y, acc[1]);
            acc[2] = fmaf(a, f23.x, acc[2]);
            acc[3] = fmaf(a, f23.y, acc[3]);
            acc[4] = fmaf(a, f45.x, acc[4]);
            acc[5] = fmaf(a, f45.y, acc[5]);
            acc[6] = fmaf(a, f67.x, acc[6]);
            acc[7] = fmaf(a, f67.y, acc[7]);
        }
    }

    // ---- reduce denominators, normalize, bias+relu, write ----
    #pragma unroll
    for (int o = 16; o > 0; o >>= 1) {
        den0 += __shfl_xor_sync(0xffffffffu, den0, o);
        den1 += __shfl_xor_sync(0xffffffffu, den1, o);
        den2 += __shfl_xor_sync(0xffffffffu, den2, o);
        den3 += __shfl_xor_sync(0xffffffffu, den3, o);
    }
    const float dh = (h == 0) ? den0 : (h == 1) ? den1 : (h == 2) ? den2 : den3;
    const float ih = 1.f / (dh + 1e-16f);

    size_t base = (size_t)d * HC + lane * 8;
    #pragma unroll
    for (int j = 0; j < 4; j++) {
        float va = fmaxf(acc[2*j]   * ih + bias[lane * 8 + 2*j],   0.f);
        float vb = fmaxf(acc[2*j+1] * ih + bias[lane * 8 + 2*j+1], 0.f);
        __half2 hv = __floats2half2_rn(va, vb);
        *(__half2*)(hout + base + 2*j) = hv;
    }
}

// ---------------- host ----------------
extern "C" void kernel_launch(void* const* d_in, const int* in_sizes, int n_in,
                              void* d_out, int out_size) {
    const float*     x   = (const float*)d_in[0];
    const long long* ei  = (const long long*)d_in[1];
    const float* W1  = (const float*)d_in[3];
    const float* as1 = (const float*)d_in[4];
    const float* ad1 = (const float*)d_in[5];
    const float* b1  = (const float*)d_in[6];
    const float* W2  = (const float*)d_in[7];
    const float* as2 = (const float*)d_in[8];
    const float* ad2 = (const float*)d_in[9];
    const float* b2  = (const float*)d_in[10];
    const float* Wfc = (const float*)d_in[11];
    const float* bfc = (const float*)d_in[12];
    float* out = (float*)d_out;

    __half *p_x16 = nullptr, *p_xh = nullptr, *p_h16 = nullptr;
    __half *p_w1 = nullptr, *p_w2 = nullptr, *p_wf = nullptr;
    float *p_asA = nullptr, *p_adA = nullptr, *p_asB = nullptr, *p_adB = nullptr;
    cudaGetSymbolAddress((void**)&p_x16, g_x16);
    cudaGetSymbolAddress((void**)&p_xh,  g_xh16);
    cudaGetSymbolAddress((void**)&p_h16, g_h16);
    cudaGetSymbolAddress((void**)&p_w1, g_w1);
    cudaGetSymbolAddress((void**)&p_w2, g_w2);
    cudaGetSymbolAddress((void**)&p_wf, g_wf);
    cudaGetSymbolAddress((void**)&p_asA, g_asrcA);
    cudaGetSymbolAddress((void**)&p_adA, g_adstA);
    cudaGetSymbolAddress((void**)&p_asB, g_asrcB);
    cudaGetSymbolAddress((void**)&p_adB, g_adstB);

    static cudaStream_t sA = nullptr;
    static cudaEvent_t evP = nullptr, evG1 = nullptr;
    if (sA == nullptr) {
        cudaStreamCreateWithFlags(&sA, cudaStreamNonBlocking);
        cudaEventCreateWithFlags(&evP,  cudaEventDisableTiming);
        cudaEventCreateWithFlags(&evG1, cudaEventDisableTiming);
    }

    const int TPB = 256;
    const int eblk = (ET + TPB - 1) / TPB;
    const int pblk = (NN * IND / 4 + TPB - 1) / TPB;
    const int gblk = (NN * 32 + TPB - 1) / TPB;
    const int mtiles = (NN + 127) / 128;   // 391

    prep_kernel<<<pblk, TPB>>>(ei, x, W1, W2, Wfc);
    cudaEventRecord(evP, 0);

    // side stream: gemm1 concurrent with edge-prep chain
    cudaStreamWaitEvent(sA, evP, 0);
    {
        dim3 grid(HC / 64, mtiles);
        gemm_mma_kernel<128, 256, false, true, true><<<grid, 256, 0, sA>>>(
            p_x16, p_w1, p_xh, nullptr, as1, ad1, p_asA, p_adA);
    }
    cudaEventRecord(evG1, sA);

    convert_hist_kernel<<<eblk, TPB>>>((const void*)ei);
    scan_partial_kernel<<<NBLK, SCAN_B>>>();
    scan_final_kernel<<<NBLK, SCAN_B>>>();
    scatter_kernel<<<eblk, TPB>>>();

    cudaStreamWaitEvent(0, evG1, 0);
    agg_kernel<<<gblk, TPB>>>(p_xh, p_asA, p_adA, b1, p_h16);
    {
        dim3 grid(HC / 64, mtiles);
        gemm_mma_kernel<256, 256, false, true, true><<<grid, 256>>>(
            p_h16, p_w2, p_xh, nullptr, as2, ad2, p_asB, p_adB);
    }
    agg_kernel<<<gblk, TPB>>>(p_xh, p_asB, p_adB, b2, p_h16);
    {
        dim3 grid(1, mtiles);
        gemm_mma_kernel<256, 64, true, false, false><<<grid, 256>>>(
            p_h16, p_wf, out, bfc, nullptr, nullptr, nullptr, nullptr);
    }
}

// round 16
// speedup vs baseline: 1.3564x; 1.3564x over previous
#include <cuda_runtime.h>
#include <cuda_fp16.h>
#include <cstdint>
#include <cfloat>

// Problem constants
#define NN     50000
#define EIN    800000
#define ET     (EIN + NN)
#define IND    128
#define HEADS  4
#define HID    64
#define HC     256
#define OUTD   64
#define NEG_SLOPE 0.2f

#define SCAN_B 256
#define NBLK   ((NN + SCAN_B - 1) / SCAN_B)

// ---------------- device scratch ----------------
__device__ __align__(16) __half g_x16 [(size_t)NN * IND];
__device__ __align__(16) __half g_xh16[(size_t)NN * HC];
__device__ __align__(16) __half g_h16 [(size_t)NN * HC];
__device__ float g_asrcA[(size_t)NN * HEADS];
__device__ float g_adstA[(size_t)NN * HEADS];
__device__ float g_asrcB[(size_t)NN * HEADS];
__device__ float g_adstB[(size_t)NN * HEADS];
__device__ __align__(16) __half g_w1[256 * 128];
__device__ __align__(16) __half g_w2[256 * 256];
__device__ __align__(16) __half g_wf[64 * 256];
__device__ int   g_deg [NN];
__device__ int   g_off [NN + 1];
__device__ int   g_cur [NN];
__device__ int   g_part[NBLK];
__device__ int   g_csrc[ET];
__device__ int   g_src [ET];
__device__ int   g_dst [ET];
__device__ int   g_is64;

__device__ __forceinline__ float lrelu(float v) {
    return v >= 0.f ? v : NEG_SLOPE * v;
}
__device__ __forceinline__ uint32_t smem_u32(const void* p) {
    uint32_t a;
    asm("{ .reg .u64 t; cvta.to.shared.u64 t, %1; cvt.u32.u64 %0, t; }" : "=r"(a) : "l"(p));
    return a;
}
__device__ __forceinline__ void cp_async16(uint32_t dst, const void* src, bool pred) {
    int sz = pred ? 16 : 0;
    asm volatile("cp.async.cg.shared.global [%0], [%1], 16, %2;"
                 :: "r"(dst), "l"(src), "r"(sz) : "memory");
}
#define CP_COMMIT() asm volatile("cp.async.commit_group;" ::: "memory")
#define CP_WAIT0()  asm volatile("cp.async.wait_group 0;" ::: "memory")
#define CP_WAIT1()  asm volatile("cp.async.wait_group 1;" ::: "memory")

// ---------------- fused prep ----------------
__global__ void prep_kernel(const long long* __restrict__ ei,
                            const float* __restrict__ x,
                            const float* __restrict__ W1,
                            const float* __restrict__ W2,
                            const float* __restrict__ Wfc) {
    int i = blockIdx.x * blockDim.x + threadIdx.x;
    if (i == 0) {
        int is64 = 1;
        for (int k = 0; k < 16; k++) {
            long long v = ei[k];
            if (v < 0 || v >= (long long)NN) { is64 = 0; break; }
        }
        g_is64 = is64;
        g_off[NN] = ET;
    }
    if (i < NN) g_deg[i] = 0;
    if (i < NN * HEADS) {
        g_asrcA[i] = 0.f; g_adstA[i] = 0.f;
        g_asrcB[i] = 0.f; g_adstB[i] = 0.f;
    }
    const int s1 = 128 * 256, s2 = s1 + 256 * 256, s3 = s2 + 256 * 64;
    if (i < s1) {
        int k = i / 256, n = i % 256;
        g_w1[n * 128 + k] = __float2half(W1[i]);
    } else if (i < s2) {
        int j = i - s1;
        int k = j / 256, n = j % 256;
        g_w2[n * 256 + k] = __float2half(W2[j]);
    } else if (i < s3) {
        int j = i - s2;
        int k = j / 64, n = j % 64;
        g_wf[n * 256 + k] = __float2half(Wfc[j]);
    }
    if (i < NN * IND / 4) {
        float4 v = *(const float4*)(x + (size_t)i * 4);
        __half2 h01 = __floats2half2_rn(v.x, v.y);
        __half2 h23 = __floats2half2_rn(v.z, v.w);
        uint2 u;
        u.x = *(uint32_t*)&h01;
        u.y = *(uint32_t*)&h23;
        *(uint2*)(g_x16 + (size_t)i * 4) = u;
    }
}

__global__ void convert_hist_kernel(const void* __restrict__ ei) {
    int i = blockIdx.x * blockDim.x + threadIdx.x;
    if (i >= ET) return;
    int s, d;
    if (i < EIN) {
        if (g_is64) {
            const long long* p = (const long long*)ei;
            s = (int)p[i];
            d = (int)p[EIN + i];
        } else {
            const int* p = (const int*)ei;
            s = p[i];
            d = p[EIN + i];
        }
    } else {
        s = d = i - EIN;
    }
    g_src[i] = s;
    g_dst[i] = d;
    atomicAdd(&g_deg[d], 1);
}

// ---------------- mma.sync fp16 + ldmatrix helpers ----------------
__device__ __forceinline__ void mma16816(float* c, const uint32_t* a, const uint32_t* b) {
    asm volatile(
        "mma.sync.aligned.m16n8k16.row.col.f32.f16.f16.f32 "
        "{%0,%1,%2,%3}, {%4,%5,%6,%7}, {%8,%9}, {%0,%1,%2,%3};"
        : "+f"(c[0]), "+f"(c[1]), "+f"(c[2]), "+f"(c[3])
        : "r"(a[0]), "r"(a[1]), "r"(a[2]), "r"(a[3]), "r"(b[0]), "r"(b[1]));
}
__device__ __forceinline__ void ldsm_x4(uint32_t* r, uint32_t addr) {
    asm volatile("ldmatrix.sync.aligned.m8n8.x4.shared.b16 {%0,%1,%2,%3}, [%4];"
                 : "=r"(r[0]), "=r"(r[1]), "=r"(r[2]), "=r"(r[3]) : "r"(addr));
}

// ---------------- tensor-core GEMM: 128 x 64 tile, 3-stage cp.async ----------------
template<int KTOT, int NTOT, bool BIAS, bool ALPHA, bool OUTF16>
__global__ void __launch_bounds__(256, 3)
gemm_mma_kernel(const __half* __restrict__ A16,
                const __half* __restrict__ B,
                void* __restrict__ Cptr,
                const float* __restrict__ bias,
                const float* __restrict__ aw_src,
                const float* __restrict__ aw_dst,
                float* __restrict__ asrc_out,
                float* __restrict__ adst_out) {
    constexpr int BN  = 64;
    constexpr int RS  = 40;
    constexpr int NF  = 2;
    constexpr int NC  = KTOT / 32;
    constexpr uint32_t BUF_BYTES = (uint32_t)(128 + BN) * RS * 2u;

    __shared__ __half sm[3 * (128 + BN) * RS];   // 45 KB

    const int tid  = threadIdx.x;
    const int wid  = tid >> 5, lane = tid & 31;
    const int wm   = wid & 1, wn = wid >> 1;
    const int row0 = blockIdx.y * 128;
    const int col0 = blockIdx.x * BN;

    float acc[4][NF][4];
    #pragma unroll
    for (int i = 0; i < 4; i++)
        #pragma unroll
        for (int j = 0; j < NF; j++)
            #pragma unroll
            for (int q = 0; q < 4; q++) acc[i][j][q] = 0.f;

    const uint32_t smBase = smem_u32(sm);

    auto stage = [&](int c) {
        uint32_t base = smBase + (uint32_t)(c % 3) * BUF_BYTES;
        #pragma unroll
        for (int q = 0; q < 2; q++) {
            int idx = tid + q * 256;
            int row = idx >> 2, c8 = (idx & 3) * 8;
            int gr = row0 + row;
            bool ok = (gr < NN);
            const __half* src = A16 + (size_t)(ok ? gr : 0) * KTOT + c * 32 + c8;
            cp_async16(base + (uint32_t)(row * RS + c8) * 2u, src, ok);
        }
        {
            int row = tid >> 2, c8 = (tid & 3) * 8;
            cp_async16(base + (uint32_t)((128 + row) * RS + c8) * 2u,
                       B + (size_t)(col0 + row) * KTOT + c * 32 + c8, true);
        }
        CP_COMMIT();
    };

    stage(0);
    if (NC > 1) stage(1);

    const int arow = (lane >> 2);
    const int acol = (lane & 3) * 2;
    const int aLaneRow = wm * 64 + (lane & 7) + ((lane >> 3) & 1) * 8;
    const uint32_t aLaneK = (lane >> 4) * 16;
    const int bLaneRow = 128 + wn * 16 + ((lane >> 4) & 1) * 8 + (lane & 7);
    const uint32_t bLaneH = ((lane >> 3) & 1) * 16;

    for (int c = 0; c < NC; c++) {
        if (c + 1 < NC) CP_WAIT1(); else CP_WAIT0();
        __syncthreads();
        if (c + 2 < NC) stage(c + 2);

        const uint32_t base = smBase + (uint32_t)(c % 3) * BUF_BYTES;
        #pragma unroll
        for (int ks = 0; ks < 2; ks++) {
            uint32_t br[4];
            ldsm_x4(br, base + (uint32_t)bLaneRow * 80u + (uint32_t)ks * 32u + bLaneH);
            uint32_t b0[2] = {br[0], br[1]};
            uint32_t b1[2] = {br[2], br[3]};
            #pragma unroll
            for (int i = 0; i < 4; i++) {
                uint32_t a[4];
                ldsm_x4(a, base + (uint32_t)(aLaneRow + i * 16) * 80u + (uint32_t)ks * 32u + aLaneK);
                mma16816(acc[i][0], a, b0);
                mma16816(acc[i][1], a, b1);
            }
        }
        __syncthreads();
    }

    // ---- epilogue: write C ----
    #pragma unroll
    for (int i = 0; i < 4; i++) {
        int r = row0 + wm * 64 + i * 16 + arow;
        #pragma unroll
        for (int j = 0; j < NF; j++) {
            int c = col0 + wn * 16 + j * 8 + acol;
            if (OUTF16) {
                __half* C16 = (__half*)Cptr;
                if (r < NN) {
                    __half2 v = __floats2half2_rn(acc[i][j][0], acc[i][j][1]);
                    *(__half2*)(C16 + (size_t)r * NTOT + c) = v;
                }
                if (r + 8 < NN) {
                    __half2 v = __floats2half2_rn(acc[i][j][2], acc[i][j][3]);
                    *(__half2*)(C16 + (size_t)(r + 8) * NTOT + c) = v;
                }
            } else {
                float* C = (float*)Cptr;
                float bx = 0.f, by = 0.f;
                if (BIAS) { bx = bias[c]; by = bias[c + 1]; }
                if (r < NN) {
                    float2 v = make_float2(acc[i][j][0] + bx, acc[i][j][1] + by);
                    *(float2*)(C + (size_t)r * NTOT + c) = v;
                }
                if (r + 8 < NN) {
                    float2 v = make_float2(acc[i][j][2] + bx, acc[i][j][3] + by);
                    *(float2*)(C + (size_t)(r + 8) * NTOT + c) = v;
                }
            }
        }
    }

    // ---- epilogue: fused alpha accumulation (NTOT == HC case) ----
    if (ALPHA) {
        const int hw = col0 >> 6;
        #pragma unroll
        for (int i = 0; i < 4; i++) {
            float ss0 = 0.f, sd0 = 0.f, ss1 = 0.f, sd1 = 0.f;
            #pragma unroll
            for (int j = 0; j < NF; j++) {
                #pragma unroll
                for (int qq = 0; qq < 2; qq++) {
                    int c = col0 + wn * 16 + j * 8 + acol + qq;
                    float ws = aw_src[c], wd = aw_dst[c];
                    ss0 += acc[i][j][qq]     * ws;
                    sd0 += acc[i][j][qq]     * wd;
                    ss1 += acc[i][j][2 + qq] * ws;
                    sd1 += acc[i][j][2 + qq] * wd;
                }
            }
            #pragma unroll
            for (int o = 1; o < 4; o <<= 1) {
                ss0 += __shfl_xor_sync(0xffffffffu, ss0, o);
                sd0 += __shfl_xor_sync(0xffffffffu, sd0, o);
                ss1 += __shfl_xor_sync(0xffffffffu, ss1, o);
                sd1 += __shfl_xor_sync(0xffffffffu, sd1, o);
            }
            if ((lane & 3) == 0) {
                int r = row0 + wm * 64 + i * 16 + arow;
                if (r < NN) {
                    atomicAdd(&asrc_out[r * 4 + hw], ss0);
                    atomicAdd(&adst_out[r * 4 + hw], sd0);
                }
                if (r + 8 < NN) {
                    atomicAdd(&asrc_out[(r + 8) * 4 + hw], ss1);
                    atomicAdd(&adst_out[(r + 8) * 4 + hw], sd1);
                }
            }
        }
    }
}

// ---------------- scan (2-phase, device-wide) ----------------
__device__ __forceinline__ int block_excl_scan(int v, int t, int* tot) {
    __shared__ int ws[8];
    int lane = t & 31, w = t >> 5;
    int x = v;
    #pragma unroll
    for (int o = 1; o < 32; o <<= 1) {
        int y = __shfl_up_sync(0xffffffffu, x, o);
        if (lane >= o) x += y;
    }
    if (lane == 31) ws[w] = x;
    __syncthreads();
    if (w == 0) {
        int z = (lane < 8) ? ws[lane] : 0;
        #pragma unroll
        for (int o = 1; o < 8; o <<= 1) {
            int y = __shfl_up_sync(0xffffffffu, z, o);
            if (lane >= o) z += y;
        }
        if (lane < 8) ws[lane] = z;
    }
    __syncthreads();
    int base = (w > 0) ? ws[w - 1] : 0;
    int total = ws[7];
    __syncthreads();
    *tot = total;
    return base + x - v;
}

__global__ void scan_partial_kernel() {
    int i = blockIdx.x * SCAN_B + threadIdx.x;
    int v = (i < NN) ? g_deg[i] : 0;
    int tot;
    block_excl_scan(v, threadIdx.x, &tot);
    if (threadIdx.x == 0) g_part[blockIdx.x] = tot;
}

__global__ void scan_final_kernel() {
    __shared__ int sred[8];
    __shared__ int sbase;
    int t = threadIdx.x;
    int lane = t & 31, w = t >> 5;

    int pv = (t < blockIdx.x && t < NBLK) ? g_part[t] : 0;
    #pragma unroll
    for (int o = 16; o > 0; o >>= 1) pv += __shfl_xor_sync(0xffffffffu, pv, o);
    if (lane == 0) sred[w] = pv;
    __syncthreads();
    if (t == 0) {
        int s = 0;
        #pragma unroll
        for (int q = 0; q < 8; q++) s += sred[q];
        sbase = s;
    }
    __syncthreads();

    int i = blockIdx.x * SCAN_B + t;
    int v = (i < NN) ? g_deg[i] : 0;
    int tot;
    int excl = block_excl_scan(v, t, &tot) + sbase;
    if (i < NN) {
        g_off[i] = excl;
        g_cur[i] = excl;
    }
}

__global__ void scatter_kernel() {
    int i = blockIdx.x * blockDim.x + threadIdx.x;
    if (i >= ET) return;
    int d = g_dst[i];
    int pos = atomicAdd(&g_cur[d], 1);
    g_csrc[pos] = g_src[i];
}

// ---------------- fused softmax + aggregation: SINGLE PASS (unshifted softmax) ----
// lane owns channels [lane*8, lane*8+8), head = lane>>3.
// For each edge: u = exp(lrelu(asrc+adst)); den += u; acc += u*msg.
// Normalize in epilogue. No max pass: logits are O(few sigma), exp is safe.
__global__ void agg_kernel(const __half* __restrict__ msg,
                           const float* __restrict__ asrc,
                           const float* __restrict__ adstv,
                           const float* __restrict__ bias,
                           __half* __restrict__ hout) {
    int warp = (blockIdx.x * blockDim.x + threadIdx.x) >> 5;
    int lane = threadIdx.x & 31;
    if (warp >= NN) return;
    const int d = warp;
    const int beg = g_off[d], end = g_off[d + 1];
    const int h = lane >> 3;
    const float adh = adstv[d * 4 + h];

    float den = 0.f;
    float acc[8] = {};
    const __half* xrow = msg + (size_t)lane * 8;

    for (int p = beg; p < end; p++) {
        int s = g_csrc[p];
        float e = lrelu(asrc[s * 4 + h] + adh);
        float u = __expf(e);
        den += u;
        uint4 v = *(const uint4*)(xrow + (size_t)s * HC);
        __half2 h01 = *(__half2*)&v.x;
        __half2 h23 = *(__half2*)&v.y;
        __half2 h45 = *(__half2*)&v.z;
        __half2 h67 = *(__half2*)&v.w;
        float2 f01 = __half22float2(h01);
        float2 f23 = __half22float2(h23);
        float2 f45 = __half22float2(h45);
        float2 f67 = __half22float2(h67);
        acc[0] = fmaf(u, f01.x, acc[0]);
        acc[1] = fmaf(u, f01.y, acc[1]);
        acc[2] = fmaf(u, f23.x, acc[2]);
        acc[3] = fmaf(u, f23.y, acc[3]);
        acc[4] = fmaf(u, f45.x, acc[4]);
        acc[5] = fmaf(u, f45.y, acc[5]);
        acc[6] = fmaf(u, f67.x, acc[6]);
        acc[7] = fmaf(u, f67.y, acc[7]);
    }

    const float ih = 1.f / (den + 1e-16f);

    size_t base = (size_t)d * HC + lane * 8;
    #pragma unroll
    for (int j = 0; j < 4; j++) {
        float va = fmaxf(acc[2*j]   * ih + bias[lane * 8 + 2*j],   0.f);
        float vb = fmaxf(acc[2*j+1] * ih + bias[lane * 8 + 2*j+1], 0.f);
        __half2 hv = __floats2half2_rn(va, vb);
        *(__half2*)(hout + base + 2*j) = hv;
    }
}

// ---------------- host ----------------
extern "C" void kernel_launch(void* const* d_in, const int* in_sizes, int n_in,
                              void* d_out, int out_size) {
    const float*     x   = (const float*)d_in[0];
    const long long* ei  = (const long long*)d_in[1];
    const float* W1  = (const float*)d_in[3];
    const float* as1 = (const float*)d_in[4];
    const float* ad1 = (const float*)d_in[5];
    const float* b1  = (const float*)d_in[6];
    const float* W2  = (const float*)d_in[7];
    const float* as2 = (const float*)d_in[8];
    const float* ad2 = (const float*)d_in[9];
    const float* b2  = (const float*)d_in[10];
    const float* Wfc = (const float*)d_in[11];
    const float* bfc = (const float*)d_in[12];
    float* out = (float*)d_out;

    __half *p_x16 = nullptr, *p_xh = nullptr, *p_h16 = nullptr;
    __half *p_w1 = nullptr, *p_w2 = nullptr, *p_wf = nullptr;
    float *p_asA = nullptr, *p_adA = nullptr, *p_asB = nullptr, *p_adB = nullptr;
    cudaGetSymbolAddress((void**)&p_x16, g_x16);
    cudaGetSymbolAddress((void**)&p_xh,  g_xh16);
    cudaGetSymbolAddress((void**)&p_h16, g_h16);
    cudaGetSymbolAddress((void**)&p_w1, g_w1);
    cudaGetSymbolAddress((void**)&p_w2, g_w2);
    cudaGetSymbolAddress((void**)&p_wf, g_wf);
    cudaGetSymbolAddress((void**)&p_asA, g_asrcA);
    cudaGetSymbolAddress((void**)&p_adA, g_adstA);
    cudaGetSymbolAddress((void**)&p_asB, g_asrcB);
    cudaGetSymbolAddress((void**)&p_adB, g_adstB);

    static cudaStream_t sA = nullptr;
    static cudaEvent_t evP = nullptr, evG1 = nullptr;
    if (sA == nullptr) {
        cudaStreamCreateWithFlags(&sA, cudaStreamNonBlocking);
        cudaEventCreateWithFlags(&evP,  cudaEventDisableTiming);
        cudaEventCreateWithFlags(&evG1, cudaEventDisableTiming);
    }

    const int TPB = 256;
    const int eblk = (ET + TPB - 1) / TPB;
    const int pblk = (NN * IND / 4 + TPB - 1) / TPB;
    const int gblk = (NN * 32 + TPB - 1) / TPB;
    const int mtiles = (NN + 127) / 128;   // 391

    prep_kernel<<<pblk, TPB>>>(ei, x, W1, W2, Wfc);
    cudaEventRecord(evP, 0);

    // side stream: gemm1 concurrent with edge-prep chain
    cudaStreamWaitEvent(sA, evP, 0);
    {
        dim3 grid(HC / 64, mtiles);
        gemm_mma_kernel<128, 256, false, true, true><<<grid, 256, 0, sA>>>(
            p_x16, p_w1, p_xh, nullptr, as1, ad1, p_asA, p_adA);
    }
    cudaEventRecord(evG1, sA);

    convert_hist_kernel<<<eblk, TPB>>>((const void*)ei);
    scan_partial_kernel<<<NBLK, SCAN_B>>>();
    scan_final_kernel<<<NBLK, SCAN_B>>>();
    scatter_kernel<<<eblk, TPB>>>();

    cudaStreamWaitEvent(0, evG1, 0);
    agg_kernel<<<gblk, TPB>>>(p_xh, p_asA, p_adA, b1, p_h16);
    {
        dim3 grid(HC / 64, mtiles);
        gemm_mma_kernel<256, 256, false, true, true><<<grid, 256>>>(
            p_h16, p_w2, p_xh, nullptr, as2, ad2, p_asB, p_adB);
    }
    agg_kernel<<<gblk, TPB>>>(p_xh, p_asB, p_adB, b2, p_h16);
    {
        dim3 grid(1, mtiles);
        gemm_mma_kernel<256, 64, true, false, false><<<grid, 256>>>(
            p_h16, p_wf, out, bfc, nullptr, nullptr, nullptr, nullptr);
    }
}

// round 17
// speedup vs baseline: 1.3897x; 1.0245x over previous
#include <cuda_runtime.h>
#include <cuda_fp16.h>
#include <cstdint>
#include <cfloat>

// Problem constants
#define NN     50000
#define EIN    800000
#define ET     (EIN + NN)
#define IND    128
#define HEADS  4
#define HID    64
#define HC     256
#define OUTD   64
#define NEG_SLOPE 0.2f

#define SCAN_B 256
#define NBLK   ((NN + SCAN_B - 1) / SCAN_B)

// ---------------- device scratch ----------------
__device__ __align__(16) __half g_x16 [(size_t)NN * IND];
__device__ __align__(16) __half g_xh16[(size_t)NN * HC];
__device__ __align__(16) __half g_h16 [(size_t)NN * HC];
__device__ float g_asrcA[(size_t)NN * HEADS];
__device__ float g_adstA[(size_t)NN * HEADS];
__device__ float g_asrcB[(size_t)NN * HEADS];
__device__ float g_adstB[(size_t)NN * HEADS];
__device__ __align__(16) __half g_w1[256 * 128];
__device__ __align__(16) __half g_w2[256 * 256];
__device__ __align__(16) __half g_wf[64 * 256];
__device__ int   g_deg [NN];
__device__ int   g_off [NN + 1];
__device__ int   g_cur [NN];
__device__ int   g_part[NBLK];
__device__ int   g_csrc[ET];
__device__ int   g_src [ET];
__device__ int   g_dst [ET];
__device__ int   g_is64;

__device__ __forceinline__ float lrelu(float v) {
    return v >= 0.f ? v : NEG_SLOPE * v;
}
__device__ __forceinline__ uint32_t smem_u32(const void* p) {
    uint32_t a;
    asm("{ .reg .u64 t; cvta.to.shared.u64 t, %1; cvt.u32.u64 %0, t; }" : "=r"(a) : "l"(p));
    return a;
}
__device__ __forceinline__ void cp_async16(uint32_t dst, const void* src, bool pred) {
    int sz = pred ? 16 : 0;
    asm volatile("cp.async.cg.shared.global [%0], [%1], 16, %2;"
                 :: "r"(dst), "l"(src), "r"(sz) : "memory");
}
#define CP_COMMIT() asm volatile("cp.async.commit_group;" ::: "memory")
#define CP_WAIT0()  asm volatile("cp.async.wait_group 0;" ::: "memory")
#define CP_WAIT1()  asm volatile("cp.async.wait_group 1;" ::: "memory")

// ---------------- prep A: detect + zero (deg, alpha accumulators) ----------------
__global__ void prep_a_kernel(const long long* __restrict__ ei) {
    int i = blockIdx.x * blockDim.x + threadIdx.x;
    if (i == 0) {
        int is64 = 1;
        for (int k = 0; k < 16; k++) {
            long long v = ei[k];
            if (v < 0 || v >= (long long)NN) { is64 = 0; break; }
        }
        g_is64 = is64;
        g_off[NN] = ET;
    }
    if (i < NN) g_deg[i] = 0;
    if (i < NN * HEADS) {
        g_asrcA[i] = 0.f; g_adstA[i] = 0.f;
        g_asrcB[i] = 0.f; g_adstB[i] = 0.f;
    }
}

// ---------------- prep B: weight + x fp16 conversion ----------------
__global__ void prep_b_kernel(const float* __restrict__ x,
                              const float* __restrict__ W1,
                              const float* __restrict__ W2,
                              const float* __restrict__ Wfc) {
    int i = blockIdx.x * blockDim.x + threadIdx.x;
    const int s1 = 128 * 256, s2 = s1 + 256 * 256, s3 = s2 + 256 * 64;
    if (i < s1) {
        int k = i / 256, n = i % 256;
        g_w1[n * 128 + k] = __float2half(W1[i]);
    } else if (i < s2) {
        int j = i - s1;
        int k = j / 256, n = j % 256;
        g_w2[n * 256 + k] = __float2half(W2[j]);
    } else if (i < s3) {
        int j = i - s2;
        int k = j / 64, n = j % 64;
        g_wf[n * 256 + k] = __float2half(Wfc[j]);
    }
    if (i < NN * IND / 4) {
        float4 v = *(const float4*)(x + (size_t)i * 4);
        __half2 h01 = __floats2half2_rn(v.x, v.y);
        __half2 h23 = __floats2half2_rn(v.z, v.w);
        uint2 u;
        u.x = *(uint32_t*)&h01;
        u.y = *(uint32_t*)&h23;
        *(uint2*)(g_x16 + (size_t)i * 4) = u;
    }
}

__global__ void convert_hist_kernel(const void* __restrict__ ei) {
    int i = blockIdx.x * blockDim.x + threadIdx.x;
    if (i >= ET) return;
    int s, d;
    if (i < EIN) {
        if (g_is64) {
            const long long* p = (const long long*)ei;
            s = (int)p[i];
            d = (int)p[EIN + i];
        } else {
            const int* p = (const int*)ei;
            s = p[i];
            d = p[EIN + i];
        }
    } else {
        s = d = i - EIN;
    }
    g_src[i] = s;
    g_dst[i] = d;
    atomicAdd(&g_deg[d], 1);
}

// ---------------- mma.sync fp16 + ldmatrix helpers ----------------
__device__ __forceinline__ void mma16816(float* c, const uint32_t* a, const uint32_t* b) {
    asm volatile(
        "mma.sync.aligned.m16n8k16.row.col.f32.f16.f16.f32 "
        "{%0,%1,%2,%3}, {%4,%5,%6,%7}, {%8,%9}, {%0,%1,%2,%3};"
        : "+f"(c[0]), "+f"(c[1]), "+f"(c[2]), "+f"(c[3])
        : "r"(a[0]), "r"(a[1]), "r"(a[2]), "r"(a[3]), "r"(b[0]), "r"(b[1]));
}
__device__ __forceinline__ void ldsm_x4(uint32_t* r, uint32_t addr) {
    asm volatile("ldmatrix.sync.aligned.m8n8.x4.shared.b16 {%0,%1,%2,%3}, [%4];"
                 : "=r"(r[0]), "=r"(r[1]), "=r"(r[2]), "=r"(r[3]) : "r"(addr));
}

// ---------------- tensor-core GEMM: 128 x 64 tile, 3-stage cp.async ----------------
template<int KTOT, int NTOT, bool BIAS, bool ALPHA, bool OUTF16>
__global__ void __launch_bounds__(256, 3)
gemm_mma_kernel(const __half* __restrict__ A16,
                const __half* __restrict__ B,
                void* __restrict__ Cptr,
                const float* __restrict__ bias,
                const float* __restrict__ aw_src,
                const float* __restrict__ aw_dst,
                float* __restrict__ asrc_out,
                float* __restrict__ adst_out) {
    constexpr int BN  = 64;
    constexpr int RS  = 40;
    constexpr int NF  = 2;
    constexpr int NC  = KTOT / 32;
    constexpr uint32_t BUF_BYTES = (uint32_t)(128 + BN) * RS * 2u;

    __shared__ __half sm[3 * (128 + BN) * RS];   // 45 KB

    const int tid  = threadIdx.x;
    const int wid  = tid >> 5, lane = tid & 31;
    const int wm   = wid & 1, wn = wid >> 1;
    const int row0 = blockIdx.y * 128;
    const int col0 = blockIdx.x * BN;

    float acc[4][NF][4];
    #pragma unroll
    for (int i = 0; i < 4; i++)
        #pragma unroll
        for (int j = 0; j < NF; j++)
            #pragma unroll
            for (int q = 0; q < 4; q++) acc[i][j][q] = 0.f;

    const uint32_t smBase = smem_u32(sm);

    auto stage = [&](int c) {
        uint32_t base = smBase + (uint32_t)(c % 3) * BUF_BYTES;
        #pragma unroll
        for (int q = 0; q < 2; q++) {
            int idx = tid + q * 256;
            int row = idx >> 2, c8 = (idx & 3) * 8;
            int gr = row0 + row;
            bool ok = (gr < NN);
            const __half* src = A16 + (size_t)(ok ? gr : 0) * KTOT + c * 32 + c8;
            cp_async16(base + (uint32_t)(row * RS + c8) * 2u, src, ok);
        }
        {
            int row = tid >> 2, c8 = (tid & 3) * 8;
            cp_async16(base + (uint32_t)((128 + row) * RS + c8) * 2u,
                       B + (size_t)(col0 + row) * KTOT + c * 32 + c8, true);
        }
        CP_COMMIT();
    };

    stage(0);
    if (NC > 1) stage(1);

    const int arow = (lane >> 2);
    const int acol = (lane & 3) * 2;
    const int aLaneRow = wm * 64 + (lane & 7) + ((lane >> 3) & 1) * 8;
    const uint32_t aLaneK = (lane >> 4) * 16;
    const int bLaneRow = 128 + wn * 16 + ((lane >> 4) & 1) * 8 + (lane & 7);
    const uint32_t bLaneH = ((lane >> 3) & 1) * 16;

    for (int c = 0; c < NC; c++) {
        if (c + 1 < NC) CP_WAIT1(); else CP_WAIT0();
        __syncthreads();
        if (c + 2 < NC) stage(c + 2);

        const uint32_t base = smBase + (uint32_t)(c % 3) * BUF_BYTES;
        #pragma unroll
        for (int ks = 0; ks < 2; ks++) {
            uint32_t br[4];
            ldsm_x4(br, base + (uint32_t)bLaneRow * 80u + (uint32_t)ks * 32u + bLaneH);
            uint32_t b0[2] = {br[0], br[1]};
            uint32_t b1[2] = {br[2], br[3]};
            #pragma unroll
            for (int i = 0; i < 4; i++) {
                uint32_t a[4];
                ldsm_x4(a, base + (uint32_t)(aLaneRow + i * 16) * 80u + (uint32_t)ks * 32u + aLaneK);
                mma16816(acc[i][0], a, b0);
                mma16816(acc[i][1], a, b1);
            }
        }
        __syncthreads();
    }

    // ---- epilogue: write C ----
    #pragma unroll
    for (int i = 0; i < 4; i++) {
        int r = row0 + wm * 64 + i * 16 + arow;
        #pragma unroll
        for (int j = 0; j < NF; j++) {
            int c = col0 + wn * 16 + j * 8 + acol;
            if (OUTF16) {
                __half* C16 = (__half*)Cptr;
                if (r < NN) {
                    __half2 v = __floats2half2_rn(acc[i][j][0], acc[i][j][1]);
                    *(__half2*)(C16 + (size_t)r * NTOT + c) = v;
                }
                if (r + 8 < NN) {
                    __half2 v = __floats2half2_rn(acc[i][j][2], acc[i][j][3]);
                    *(__half2*)(C16 + (size_t)(r + 8) * NTOT + c) = v;
                }
            } else {
                float* C = (float*)Cptr;
                float bx = 0.f, by = 0.f;
                if (BIAS) { bx = bias[c]; by = bias[c + 1]; }
                if (r < NN) {
                    float2 v = make_float2(acc[i][j][0] + bx, acc[i][j][1] + by);
                    *(float2*)(C + (size_t)r * NTOT + c) = v;
                }
                if (r + 8 < NN) {
                    float2 v = make_float2(acc[i][j][2] + bx, acc[i][j][3] + by);
                    *(float2*)(C + (size_t)(r + 8) * NTOT + c) = v;
                }
            }
        }
    }

    // ---- epilogue: fused alpha accumulation (NTOT == HC case) ----
    if (ALPHA) {
        const int hw = col0 >> 6;
        #pragma unroll
        for (int i = 0; i < 4; i++) {
            float ss0 = 0.f, sd0 = 0.f, ss1 = 0.f, sd1 = 0.f;
            #pragma unroll
            for (int j = 0; j < NF; j++) {
                #pragma unroll
                for (int qq = 0; qq < 2; qq++) {
                    int c = col0 + wn * 16 + j * 8 + acol + qq;
                    float ws = aw_src[c], wd = aw_dst[c];
                    ss0 += acc[i][j][qq]     * ws;
                    sd0 += acc[i][j][qq]     * wd;
                    ss1 += acc[i][j][2 + qq] * ws;
                    sd1 += acc[i][j][2 + qq] * wd;
                }
            }
            #pragma unroll
            for (int o = 1; o < 4; o <<= 1) {
                ss0 += __shfl_xor_sync(0xffffffffu, ss0, o);
                sd0 += __shfl_xor_sync(0xffffffffu, sd0, o);
                ss1 += __shfl_xor_sync(0xffffffffu, ss1, o);
                sd1 += __shfl_xor_sync(0xffffffffu, sd1, o);
            }
            if ((lane & 3) == 0) {
                int r = row0 + wm * 64 + i * 16 + arow;
                if (r < NN) {
                    atomicAdd(&asrc_out[r * 4 + hw], ss0);
                    atomicAdd(&adst_out[r * 4 + hw], sd0);
                }
                if (r + 8 < NN) {
                    atomicAdd(&asrc_out[(r + 8) * 4 + hw], ss1);
                    atomicAdd(&adst_out[(r + 8) * 4 + hw], sd1);
                }
            }
        }
    }
}

// ---------------- scan (2-phase, device-wide) ----------------
__device__ __forceinline__ int block_excl_scan(int v, int t, int* tot) {
    __shared__ int ws[8];
    int lane = t & 31, w = t >> 5;
    int x = v;
    #pragma unroll
    for (int o = 1; o < 32; o <<= 1) {
        int y = __shfl_up_sync(0xffffffffu, x, o);
        if (lane >= o) x += y;
    }
    if (lane == 31) ws[w] = x;
    __syncthreads();
    if (w == 0) {
        int z = (lane < 8) ? ws[lane] : 0;
        #pragma unroll
        for (int o = 1; o < 8; o <<= 1) {
            int y = __shfl_up_sync(0xffffffffu, z, o);
            if (lane >= o) z += y;
        }
        if (lane < 8) ws[lane] = z;
    }
    __syncthreads();
    int base = (w > 0) ? ws[w - 1] : 0;
    int total = ws[7];
    __syncthreads();
    *tot = total;
    return base + x - v;
}

__global__ void scan_partial_kernel() {
    int i = blockIdx.x * SCAN_B + threadIdx.x;
    int v = (i < NN) ? g_deg[i] : 0;
    int tot;
    block_excl_scan(v, threadIdx.x, &tot);
    if (threadIdx.x == 0) g_part[blockIdx.x] = tot;
}

__global__ void scan_final_kernel() {
    __shared__ int sred[8];
    __shared__ int sbase;
    int t = threadIdx.x;
    int lane = t & 31, w = t >> 5;

    int pv = (t < blockIdx.x && t < NBLK) ? g_part[t] : 0;
    #pragma unroll
    for (int o = 16; o > 0; o >>= 1) pv += __shfl_xor_sync(0xffffffffu, pv, o);
    if (lane == 0) sred[w] = pv;
    __syncthreads();
    if (t == 0) {
        int s = 0;
        #pragma unroll
        for (int q = 0; q < 8; q++) s += sred[q];
        sbase = s;
    }
    __syncthreads();

    int i = blockIdx.x * SCAN_B + t;
    int v = (i < NN) ? g_deg[i] : 0;
    int tot;
    int excl = block_excl_scan(v, t, &tot) + sbase;
    if (i < NN) {
        g_off[i] = excl;
        g_cur[i] = excl;
    }
}

__global__ void scatter_kernel() {
    int i = blockIdx.x * blockDim.x + threadIdx.x;
    if (i >= ET) return;
    int d = g_dst[i];
    int pos = atomicAdd(&g_cur[d], 1);
    g_csrc[pos] = g_src[i];
}

// ---------------- single-pass agg (unshifted softmax), edge loop unrolled x2 ----
__global__ void agg_kernel(const __half* __restrict__ msg,
                           const float* __restrict__ asrc,
                           const float* __restrict__ adstv,
                           const float* __restrict__ bias,
                           __half* __restrict__ hout) {
    int warp = (blockIdx.x * blockDim.x + threadIdx.x) >> 5;
    int lane = threadIdx.x & 31;
    if (warp >= NN) return;
    const int d = warp;
    const int beg = g_off[d], end = g_off[d + 1];
    const int h = lane >> 3;
    const float adh = adstv[d * 4 + h];

    float den = 0.f;
    float acc[8] = {};
    const __half* xrow = msg + (size_t)lane * 8;

    int p = beg;
    for (; p + 2 <= end; p += 2) {
        int s0 = g_csrc[p];
        int s1 = g_csrc[p + 1];
        float a0 = asrc[s0 * 4 + h];
        float a1 = asrc[s1 * 4 + h];
        uint4 v0 = *(const uint4*)(xrow + (size_t)s0 * HC);
        uint4 v1 = *(const uint4*)(xrow + (size_t)s1 * HC);
        float u0 = __expf(lrelu(a0 + adh));
        float u1 = __expf(lrelu(a1 + adh));
        den += u0 + u1;
        {
            float2 f01 = __half22float2(*(__half2*)&v0.x);
            float2 f23 = __half22float2(*(__half2*)&v0.y);
            float2 f45 = __half22float2(*(__half2*)&v0.z);
            float2 f67 = __half22float2(*(__half2*)&v0.w);
            acc[0] = fmaf(u0, f01.x, acc[0]);
            acc[1] = fmaf(u0, f01.y, acc[1]);
            acc[2] = fmaf(u0, f23.x, acc[2]);
            acc[3] = fmaf(u0, f23.y, acc[3]);
            acc[4] = fmaf(u0, f45.x, acc[4]);
            acc[5] = fmaf(u0, f45.y, acc[5]);
            acc[6] = fmaf(u0, f67.x, acc[6]);
            acc[7] = fmaf(u0, f67.y, acc[7]);
        }
        {
            float2 f01 = __half22float2(*(__half2*)&v1.x);
            float2 f23 = __half22float2(*(__half2*)&v1.y);
            float2 f45 = __half22float2(*(__half2*)&v1.z);
            float2 f67 = __half22float2(*(__half2*)&v1.w);
            acc[0] = fmaf(u1, f01.x, acc[0]);
            acc[1] = fmaf(u1, f01.y, acc[1]);
            acc[2] = fmaf(u1, f23.x, acc[2]);
            acc[3] = fmaf(u1, f23.y, acc[3]);
            acc[4] = fmaf(u1, f45.x, acc[4]);
            acc[5] = fmaf(u1, f45.y, acc[5]);
            acc[6] = fmaf(u1, f67.x, acc[6]);
            acc[7] = fmaf(u1, f67.y, acc[7]);
        }
    }
    if (p < end) {
        int s = g_csrc[p];
        float u = __expf(lrelu(asrc[s * 4 + h] + adh));
        den += u;
        uint4 v = *(const uint4*)(xrow + (size_t)s * HC);
        float2 f01 = __half22float2(*(__half2*)&v.x);
        float2 f23 = __half22float2(*(__half2*)&v.y);
        float2 f45 = __half22float2(*(__half2*)&v.z);
        float2 f67 = __half22float2(*(__half2*)&v.w);
        acc[0] = fmaf(u, f01.x, acc[0]);
        acc[1] = fmaf(u, f01.y, acc[1]);
        acc[2] = fmaf(u, f23.x, acc[2]);
        acc[3] = fmaf(u, f23.y, acc[3]);
        acc[4] = fmaf(u, f45.x, acc[4]);
        acc[5] = fmaf(u, f45.y, acc[5]);
        acc[6] = fmaf(u, f67.x, acc[6]);
        acc[7] = fmaf(u, f67.y, acc[7]);
    }

    const float ih = 1.f / (den + 1e-16f);

    size_t base = (size_t)d * HC + lane * 8;
    #pragma unroll
    for (int j = 0; j < 4; j++) {
        float va = fmaxf(acc[2*j]   * ih + bias[lane * 8 + 2*j],   0.f);
        float vb = fmaxf(acc[2*j+1] * ih + bias[lane * 8 + 2*j+1], 0.f);
        __half2 hv = __floats2half2_rn(va, vb);
        *(__half2*)(hout + base + 2*j) = hv;
    }
}

// ---------------- host ----------------
extern "C" void kernel_launch(void* const* d_in, const int* in_sizes, int n_in,
                              void* d_out, int out_size) {
    const float*     x   = (const float*)d_in[0];
    const long long* ei  = (const long long*)d_in[1];
    const float* W1  = (const float*)d_in[3];
    const float* as1 = (const float*)d_in[4];
    const float* ad1 = (const float*)d_in[5];
    const float* b1  = (const float*)d_in[6];
    const float* W2  = (const float*)d_in[7];
    const float* as2 = (const float*)d_in[8];
    const float* ad2 = (const float*)d_in[9];
    const float* b2  = (const float*)d_in[10];
    const float* Wfc = (const float*)d_in[11];
    const float* bfc = (const float*)d_in[12];
    float* out = (float*)d_out;

    __half *p_x16 = nullptr, *p_xh = nullptr, *p_h16 = nullptr;
    __half *p_w1 = nullptr, *p_w2 = nullptr, *p_wf = nullptr;
    float *p_asA = nullptr, *p_adA = nullptr, *p_asB = nullptr, *p_adB = nullptr;
    cudaGetSymbolAddress((void**)&p_x16, g_x16);
    cudaGetSymbolAddress((void**)&p_xh,  g_xh16);
    cudaGetSymbolAddress((void**)&p_h16, g_h16);
    cudaGetSymbolAddress((void**)&p_w1, g_w1);
    cudaGetSymbolAddress((void**)&p_w2, g_w2);
    cudaGetSymbolAddress((void**)&p_wf, g_wf);
    cudaGetSymbolAddress((void**)&p_asA, g_asrcA);
    cudaGetSymbolAddress((void**)&p_adA, g_adstA);
    cudaGetSymbolAddress((void**)&p_asB, g_asrcB);
    cudaGetSymbolAddress((void**)&p_adB, g_adstB);

    static cudaStream_t sA = nullptr;
    static cudaEvent_t evA = nullptr, evG1 = nullptr;
    if (sA == nullptr) {
        cudaStreamCreateWithFlags(&sA, cudaStreamNonBlocking);
        cudaEventCreateWithFlags(&evA,  cudaEventDisableTiming);
        cudaEventCreateWithFlags(&evG1, cudaEventDisableTiming);
    }

    const int TPB = 256;
    const int eblk = (ET + TPB - 1) / TPB;
    const int pablk = (NN * HEADS + TPB - 1) / TPB;
    const int pbblk = (NN * IND / 4 + TPB - 1) / TPB;
    const int gblk = (NN * 32 + TPB - 1) / TPB;
    const int mtiles = (NN + 127) / 128;   // 391

    // prep_a (small): detect + zeroing — required by hist AND gemm1's alpha atomics
    prep_a_kernel<<<pablk, TPB>>>(ei);
    cudaEventRecord(evA, 0);

    // side stream: conversions + gemm1, concurrent with edge-prep chain
    cudaStreamWaitEvent(sA, evA, 0);
    prep_b_kernel<<<pbblk, TPB, 0, sA>>>(x, W1, W2, Wfc);
    {
        dim3 grid(HC / 64, mtiles);
        gemm_mma_kernel<128, 256, false, true, true><<<grid, 256, 0, sA>>>(
            p_x16, p_w1, p_xh, nullptr, as1, ad1, p_asA, p_adA);
    }
    cudaEventRecord(evG1, sA);

    // main stream: edge prep
    convert_hist_kernel<<<eblk, TPB>>>((const void*)ei);
    scan_partial_kernel<<<NBLK, SCAN_B>>>();
    scan_final_kernel<<<NBLK, SCAN_B>>>();
    scatter_kernel<<<eblk, TPB>>>();

    cudaStreamWaitEvent(0, evG1, 0);
    agg_kernel<<<gblk, TPB>>>(p_xh, p_asA, p_adA, b1, p_h16);
    {
        dim3 grid(HC / 64, mtiles);
        gemm_mma_kernel<256, 256, false, true, true><<<grid, 256>>>(
            p_h16, p_w2, p_xh, nullptr, as2, ad2, p_asB, p_adB);
    }
    agg_kernel<<<gblk, TPB>>>(p_xh, p_asB, p_adB, b2, p_h16);
    {
        dim3 grid(1, mtiles);
        gemm_mma_kernel<256, 64, true, false, false><<<grid, 256>>>(
            p_h16, p_wf, out, bfc, nullptr, nullptr, nullptr, nullptr);
    }
}